// round 15
// baseline (speedup 1.0000x reference)
#include <cuda_runtime.h>
#include <cuda_bf16.h>
#include <stdint.h>
#include <math.h>

#define B_  4
#define S_  512
#define D_  768
#define H_  12
#define DH_ 64
#define SD_ 30
#define BS_ (B_*S_)   // 2048

// ---- scratch ----
__device__ float g_q  [B_*H_*S_*DH_];                 // fp32 q (for qws)
__device__ __nv_bfloat16 g_qh [B_*H_*S_*DH_];         // bf16 splits, (bh,s,d)
__device__ __nv_bfloat16 g_ql [B_*H_*S_*DH_];
__device__ __nv_bfloat16 g_kh [B_*H_*S_*DH_];
__device__ __nv_bfloat16 g_kl [B_*H_*S_*DH_];
__device__ __nv_bfloat16 g_vhT[B_*H_*S_*DH_];         // transposed (bh,d,s)
__device__ __nv_bfloat16 g_vlT[B_*H_*S_*DH_];
__device__ float g_qws[B_*H_*S_*SD_];
__device__ float g_qb [B_*H_*S_];
__device__ float g_attn[(size_t)B_*H_*S_*S_];
__device__ float g_ctxa[B_*H_*S_*DH_];
__device__ float g_astp[4][B_*H_*S_*SD_];             // k-split partials
__device__ float g_ctx [BS_*D_];
__device__ float g_opp [2][BS_*D_];                   // out-proj split-K partials

// ================= helpers =================
__device__ __forceinline__ void mma_bf16(float* c, const uint32_t* a, const uint32_t* b) {
    asm volatile("mma.sync.aligned.m16n8k16.row.col.f32.bf16.bf16.f32 "
        "{%0,%1,%2,%3}, {%4,%5,%6,%7}, {%8,%9}, {%0,%1,%2,%3};"
        : "+f"(c[0]), "+f"(c[1]), "+f"(c[2]), "+f"(c[3])
        : "r"(a[0]), "r"(a[1]), "r"(a[2]), "r"(a[3]), "r"(b[0]), "r"(b[1]));
}
__device__ __forceinline__ void split_bf16(float x, __nv_bfloat16& h, __nv_bfloat16& l) {
    h = __float2bfloat16(x);
    l = __float2bfloat16(x - __bfloat162float(h));
}
__device__ __forceinline__ uint32_t pack_bf2(__nv_bfloat16 a, __nv_bfloat16 b) {
    return (uint32_t)__bfloat16_as_ushort(a) | ((uint32_t)__bfloat16_as_ushort(b) << 16);
}
__device__ __forceinline__ uint32_t smem_u32(const void* p) {
    uint32_t a;
    asm("{ .reg .u64 t; cvta.to.shared.u64 t, %1; cvt.u32.u64 %0, t; }" : "=r"(a) : "l"(p));
    return a;
}
__device__ __forceinline__ void cp16(uint32_t dst, const void* src) {
    asm volatile("cp.async.cg.shared.global [%0], [%1], 16;" :: "r"(dst), "l"(src));
}
#define CP_COMMIT() asm volatile("cp.async.commit_group;")

// ============================================================
// HMMA bf16-split GEMM (R10 structure).
// MODE 0: blockIdx.z selects q/k/v projection (fused launch); K full.
// MODE 1: X=g_ctx; blockIdx.z = split-K half; partial -> g_opp[z].
// ============================================================
template<int MODE>
__global__ void __launch_bounds__(256) gemm_mma(
    const float* __restrict__ Aq, const float* __restrict__ Ak, const float* __restrict__ Av,
    const float* __restrict__ Wq_, const float* __restrict__ Wk_, const float* __restrict__ Wv_,
    const float* __restrict__ bq_, const float* __restrict__ bk_, const float* __restrict__ bv_,
    float* __restrict__ extout)
{
    __shared__ __nv_bfloat16 sAh[128][40];
    __shared__ __nv_bfloat16 sAl[128][40];
    __shared__ __nv_bfloat16 sBh[64][40];
    __shared__ __nv_bfloat16 sBl[64][40];

    const int t = threadIdx.x;
    const int z = blockIdx.z;

    const float* X; const float* W; const float* bias; float scale = 1.0f;
    if (MODE == 0) {
        X    = (z == 0) ? Aq  : (z == 1) ? Ak  : Av;
        W    = (z == 0) ? Wq_ : (z == 1) ? Wk_ : Wv_;
        bias = (z == 0) ? bq_ : (z == 1) ? bk_ : bv_;
        if (z == 0) scale = 0.125f;
    } else {
        X = g_ctx; W = Wq_; bias = bq_;
    }
    const int m0 = blockIdx.y * 128, n0 = blockIdx.x * 64;
    const int w = t >> 5, l = t & 31;
    const int wm = (w >> 1) * 32, wn = (w & 1) * 32;
    const int lq = l >> 2, lr = l & 3;

    float C[2][4][4];
    #pragma unroll
    for (int i = 0; i < 2; i++)
        #pragma unroll
        for (int j = 0; j < 4; j++)
            #pragma unroll
            for (int p = 0; p < 4; p++) C[i][j][p] = 0.f;

    const int kcBeg = (MODE == 1) ? z * 12 : 0;
    const int kcEnd = (MODE == 1) ? z * 12 + 12 : 24;

    for (int kc = kcBeg; kc < kcEnd; kc++) {
        const int k0 = kc * 32;
        __syncthreads();
        #pragma unroll
        for (int it = 0; it < 4; it++) {
            int f = t + it * 256;
            int m = f >> 3, k4 = (f & 7) * 4;
            float4 v = *(const float4*)(X + (size_t)(m0 + m) * 768 + k0 + k4);
            __nv_bfloat16 h0,h1,h2,h3, l0,l1,l2,l3;
            split_bf16(v.x, h0, l0); split_bf16(v.y, h1, l1);
            split_bf16(v.z, h2, l2); split_bf16(v.w, h3, l3);
            *(uint2*)&sAh[m][k4] = make_uint2(pack_bf2(h0,h1), pack_bf2(h2,h3));
            *(uint2*)&sAl[m][k4] = make_uint2(pack_bf2(l0,l1), pack_bf2(l2,l3));
        }
        #pragma unroll
        for (int it = 0; it < 2; it++) {
            int f = t + it * 256;
            int kk = f >> 4, n4 = (f & 15) * 4;
            float4 v = *(const float4*)(W + (size_t)(k0 + kk) * 768 + n0 + n4);
            __nv_bfloat16 h, lo;
            split_bf16(v.x, h, lo); sBh[n4+0][kk] = h; sBl[n4+0][kk] = lo;
            split_bf16(v.y, h, lo); sBh[n4+1][kk] = h; sBl[n4+1][kk] = lo;
            split_bf16(v.z, h, lo); sBh[n4+2][kk] = h; sBl[n4+2][kk] = lo;
            split_bf16(v.w, h, lo); sBh[n4+3][kk] = h; sBl[n4+3][kk] = lo;
        }
        __syncthreads();

        #pragma unroll
        for (int s = 0; s < 2; s++) {
            const int kcl = s * 16 + lr * 2;
            uint32_t ah[2][4], al[2][4];
            #pragma unroll
            for (int i = 0; i < 2; i++) {
                int r = wm + i * 16 + lq;
                ah[i][0] = *(const uint32_t*)&sAh[r][kcl];
                ah[i][1] = *(const uint32_t*)&sAh[r + 8][kcl];
                ah[i][2] = *(const uint32_t*)&sAh[r][kcl + 8];
                ah[i][3] = *(const uint32_t*)&sAh[r + 8][kcl + 8];
                al[i][0] = *(const uint32_t*)&sAl[r][kcl];
                al[i][1] = *(const uint32_t*)&sAl[r + 8][kcl];
                al[i][2] = *(const uint32_t*)&sAl[r][kcl + 8];
                al[i][3] = *(const uint32_t*)&sAl[r + 8][kcl + 8];
            }
            uint32_t bh[4][2], bl[4][2];
            #pragma unroll
            for (int j = 0; j < 4; j++) {
                int n = wn + j * 8 + lq;
                bh[j][0] = *(const uint32_t*)&sBh[n][kcl];
                bh[j][1] = *(const uint32_t*)&sBh[n][kcl + 8];
                bl[j][0] = *(const uint32_t*)&sBl[n][kcl];
                bl[j][1] = *(const uint32_t*)&sBl[n][kcl + 8];
            }
            #pragma unroll
            for (int i = 0; i < 2; i++)
                #pragma unroll
                for (int j = 0; j < 4; j++) {
                    mma_bf16(C[i][j], ah[i], bh[j]);
                    mma_bf16(C[i][j], ah[i], bl[j]);
                    mma_bf16(C[i][j], al[i], bh[j]);
                }
        }
    }

    #pragma unroll
    for (int i = 0; i < 2; i++) {
        #pragma unroll
        for (int j = 0; j < 4; j++) {
            int rA = m0 + wm + i * 16 + lq;
            int cA = n0 + wn + j * 8 + lr * 2;
            #pragma unroll
            for (int half = 0; half < 2; half++) {
                int m = rA + half * 8;
                if (MODE == 0) {
                    float v0 = (C[i][j][half*2 + 0] + bias[cA])     * scale;
                    float v1 = (C[i][j][half*2 + 1] + bias[cA + 1]) * scale;
                    int b_i = m >> 9, s = m & 511, h = cA >> 6, d = cA & 63;
                    size_t base = (((size_t)b_i * H_ + h) * S_ + s) * DH_ + d;
                    __nv_bfloat16 h0, l0, h1, l1;
                    split_bf16(v0, h0, l0); split_bf16(v1, h1, l1);
                    if (z == 0) {
                        *(float2*)(g_q + base) = make_float2(v0, v1);
                        *(uint32_t*)&g_qh[base] = pack_bf2(h0, h1);
                        *(uint32_t*)&g_ql[base] = pack_bf2(l0, l1);
                    } else if (z == 1) {
                        *(uint32_t*)&g_kh[base] = pack_bf2(h0, h1);
                        *(uint32_t*)&g_kl[base] = pack_bf2(l0, l1);
                    } else {
                        size_t tb = ((size_t)(b_i * H_ + h) * DH_ + d) * S_ + s;
                        g_vhT[tb] = h0; g_vhT[tb + S_] = h1;
                        g_vlT[tb] = l0; g_vlT[tb + S_] = l1;
                    }
                } else {
                    // split-K partial: bias folded into split 0 only
                    float v0 = C[i][j][half*2 + 0] + ((z == 0) ? bias[cA]     : 0.f);
                    float v1 = C[i][j][half*2 + 1] + ((z == 0) ? bias[cA + 1] : 0.f);
                    *(float2*)(g_opp[z] + (size_t)m * 768 + cA) = make_float2(v0, v1);
                }
            }
        }
    }
    (void)extout;
}

// ============================================================
// merge out-proj partials: out = opp[0] + opp[1]
// ============================================================
__global__ void __launch_bounds__(256) opmerge_kernel(float* __restrict__ out)
{
    int idx = blockIdx.x * 256 + threadIdx.x;     // over BS*D/4 float4
    float4 a = *(const float4*)(g_opp[0] + (size_t)idx * 4);
    float4 b = *(const float4*)(g_opp[1] + (size_t)idx * 4);
    float4 r = make_float4(a.x + b.x, a.y + b.y, a.z + b.z, a.w + b.w);
    *(float4*)(out + (size_t)idx * 4) = r;
}

// ============================================================
// qws: smem-tiled
// ============================================================
__global__ void __launch_bounds__(128) qws2_kernel(const float* __restrict__ Wsk,
                                                   const float* __restrict__ bsk)
{
    __shared__ float sq[32][65];
    __shared__ float sw[31][64];
    const int t = threadIdx.x;
    const int r0 = blockIdx.x * 32;

    #pragma unroll
    for (int i = 0; i < 4; i++) {
        int f = t + i * 128;
        int r = f >> 4, c4 = (f & 15) * 4;
        float4 v = *(const float4*)(g_q + (size_t)(r0 + r) * 64 + c4);
        sq[r][c4] = v.x; sq[r][c4+1] = v.y; sq[r][c4+2] = v.z; sq[r][c4+3] = v.w;
    }
    #pragma unroll
    for (int i = 0; i < 4; i++) {
        int f = t + i * 128;
        if (f < 496) {
            int c = f >> 4, d4 = (f & 15) * 4;
            float4 v = (c < 30) ? *(const float4*)(Wsk + c * 64 + d4)
                                : *(const float4*)(bsk + d4);
            sw[c][d4] = v.x; sw[c][d4+1] = v.y; sw[c][d4+2] = v.z; sw[c][d4+3] = v.w;
        }
    }
    __syncthreads();

    const int row = t & 31;
    const int grp = t >> 5;
    const int c0 = grp * 8;
    float acc[8] = {};
    #pragma unroll
    for (int d = 0; d < 64; d++) {
        float qv = sq[row][d];
        #pragma unroll
        for (int j = 0; j < 8; j++) {
            int c = c0 + j;
            if (j < 7 || grp < 3) {
                float wv = (c < 30) ? sw[c][d] : sw[30][d];
                acc[j] += qv * wv;
            }
        }
    }
    int rg = r0 + row;
    if (grp < 3) {
        #pragma unroll
        for (int j = 0; j < 8; j++) g_qws[(size_t)rg*SD_ + c0 + j] = acc[j];
    } else {
        #pragma unroll
        for (int j = 0; j < 6; j++) g_qws[(size_t)rg*SD_ + 24 + j] = acc[j];
        g_qb[rg] = acc[6];
    }
}

// ============================================================
// struct scores prepass
// ============================================================
__global__ void struct_score_kernel(const float* __restrict__ structure)
{
    int b = blockIdx.z, q = blockIdx.y;
    int k = blockIdx.x * 128 + threadIdx.x;
    __shared__ float qw[H_][SD_];
    __shared__ float qb[H_];
    int t = threadIdx.x;
    for (int i = t; i < H_*SD_; i += 128) {
        int h = i / SD_, c = i % SD_;
        qw[h][c] = g_qws[(((size_t)b*H_ + h)*S_ + q)*SD_ + c];
    }
    if (t < H_) qb[t] = g_qb[((size_t)b*H_ + t)*S_ + q];
    __syncthreads();

    const float* st = structure + ((size_t)(b*S_ + q)*S_ + k) * SD_;
    float sv[SD_];
    #pragma unroll
    for (int c = 0; c < SD_; c += 2) {
        float2 v = *(const float2*)(st + c);
        sv[c] = v.x; sv[c+1] = v.y;
    }
    #pragma unroll
    for (int h = 0; h < H_; h++) {
        float acc = qb[h];
        #pragma unroll
        for (int c = 0; c < SD_; c++) acc += sv[c] * qw[h][c];
        g_attn[(((size_t)b*H_ + h)*S_ + q)*S_ + k] = acc;
    }
}

// ============================================================
// attn2 rev3b: cp.async double-buffered K/V; QK^T + bias + mask +
// softmax + P@V. Block = (b,h) x 32 q-rows, 256 threads.
// ============================================================
#define AT_SMEM 112640
__global__ void __launch_bounds__(256) attn2_kernel(const unsigned int* __restrict__ mask,
                                                    float* __restrict__ top_out)
{
    extern __shared__ char smem[];
    uint32_t sb = smem_u32(smem);
    float*          sc  = (float*)smem;
    __nv_bfloat16*  sPh = (__nv_bfloat16*)smem;
    __nv_bfloat16*  sPl = (__nv_bfloat16*)(smem + 33280);
    __nv_bfloat16*  sQh = (__nv_bfloat16*)(smem + 66560);
    __nv_bfloat16*  sQl = (__nv_bfloat16*)(smem + 71168);
    const uint32_t OF_H = 75776, OF_L = 94208;   // + buf*9216

    const int bh = blockIdx.y;
    const int b  = bh / H_;
    const int h  = bh % H_;
    const int q0 = blockIdx.x * 32;
    const __nv_bfloat16* Qh = g_qh  + (size_t)bh * S_ * DH_;
    const __nv_bfloat16* Ql = g_ql  + (size_t)bh * S_ * DH_;
    const __nv_bfloat16* Kh = g_kh  + (size_t)bh * S_ * DH_;
    const __nv_bfloat16* Kl = g_kl  + (size_t)bh * S_ * DH_;
    const __nv_bfloat16* VhT = g_vhT + (size_t)bh * S_ * DH_;   // (d,s)
    const __nv_bfloat16* VlT = g_vlT + (size_t)bh * S_ * DH_;

    const int t = threadIdx.x;
    const int w = t >> 5, l = t & 31;
    const int lq = l >> 2, lr = l & 3;
    const int crow = t >> 3, cseg = (t & 7) * 16;     // copy mapping

    // ---- stage Q ----
    {
        int row = t >> 3, d8 = (t & 7) * 8;
        *(uint4*)&sQh[row*72 + d8] = *(const uint4*)(Qh + (size_t)(q0 + row)*64 + d8);
        *(uint4*)&sQl[row*72 + d8] = *(const uint4*)(Ql + (size_t)(q0 + row)*64 + d8);
    }

    // ---- QK^T: 8 chunks of 64 k-rows, double-buffered cp.async ----
    #define KCOPY(c, buf) do { \
        const char* bH = (const char*)Kh + (size_t)(c)*8192; \
        const char* bL = (const char*)Kl + (size_t)(c)*8192; \
        cp16(sb + OF_H + (buf)*9216 + crow*144 + cseg,       bH + crow*128 + cseg); \
        cp16(sb + OF_H + (buf)*9216 + (crow+32)*144 + cseg,  bH + (crow+32)*128 + cseg); \
        cp16(sb + OF_L + (buf)*9216 + crow*144 + cseg,       bL + crow*128 + cseg); \
        cp16(sb + OF_L + (buf)*9216 + (crow+32)*144 + cseg,  bL + (crow+32)*128 + cseg); \
    } while (0)

    KCOPY(0, 0); CP_COMMIT();
    for (int c = 0; c < 8; c++) {
        const int buf = c & 1;
        if (c < 7) { KCOPY(c + 1, buf ^ 1); CP_COMMIT();
                     asm volatile("cp.async.wait_group 1;"); }
        else       { asm volatile("cp.async.wait_group 0;"); }
        __syncthreads();

        const __nv_bfloat16* kbh = (const __nv_bfloat16*)(smem + OF_H + buf*9216);
        const __nv_bfloat16* kbl = (const __nv_bfloat16*)(smem + OF_L + buf*9216);

        float C[2][4];
        #pragma unroll
        for (int i = 0; i < 2; i++)
            #pragma unroll
            for (int p = 0; p < 4; p++) C[i][p] = 0.f;

        #pragma unroll
        for (int ks = 0; ks < 4; ks++) {
            const int kc = ks * 16 + lr * 2;
            uint32_t ah[2][4], al[2][4];
            #pragma unroll
            for (int mf = 0; mf < 2; mf++) {
                int r = mf * 16 + lq;
                ah[mf][0] = *(const uint32_t*)&sQh[r*72 + kc];
                ah[mf][1] = *(const uint32_t*)&sQh[(r+8)*72 + kc];
                ah[mf][2] = *(const uint32_t*)&sQh[r*72 + kc + 8];
                ah[mf][3] = *(const uint32_t*)&sQh[(r+8)*72 + kc + 8];
                al[mf][0] = *(const uint32_t*)&sQl[r*72 + kc];
                al[mf][1] = *(const uint32_t*)&sQl[(r+8)*72 + kc];
                al[mf][2] = *(const uint32_t*)&sQl[r*72 + kc + 8];
                al[mf][3] = *(const uint32_t*)&sQl[(r+8)*72 + kc + 8];
            }
            uint32_t bhf[2], blf[2];
            int n = w * 8 + lq;
            bhf[0] = *(const uint32_t*)&kbh[n*72 + kc];
            bhf[1] = *(const uint32_t*)&kbh[n*72 + kc + 8];
            blf[0] = *(const uint32_t*)&kbl[n*72 + kc];
            blf[1] = *(const uint32_t*)&kbl[n*72 + kc + 8];
            #pragma unroll
            for (int mf = 0; mf < 2; mf++) {
                mma_bf16(C[mf], ah[mf], bhf);
                mma_bf16(C[mf], ah[mf], blf);
                mma_bf16(C[mf], al[mf], bhf);
            }
        }
        #pragma unroll
        for (int mf = 0; mf < 2; mf++) {
            int col = c * 64 + w * 8 + lr * 2;
            int r = mf * 16 + lq;
            *(float2*)&sc[r*520 + col]     = make_float2(C[mf][0], C[mf][1]);
            *(float2*)&sc[(r+8)*520 + col] = make_float2(C[mf][2], C[mf][3]);
        }
        __syncthreads();
    }

    // ---- prefetch V chunk 0 (overlaps softmax) ----
    #define VCOPY(c, buf) do { \
        const char* bH = (const char*)VhT + (size_t)(c)*128; \
        const char* bL = (const char*)VlT + (size_t)(c)*128; \
        cp16(sb + OF_H + (buf)*9216 + crow*144 + cseg,       bH + (size_t)crow*1024 + cseg); \
        cp16(sb + OF_H + (buf)*9216 + (crow+32)*144 + cseg,  bH + (size_t)(crow+32)*1024 + cseg); \
        cp16(sb + OF_L + (buf)*9216 + crow*144 + cseg,       bL + (size_t)crow*1024 + cseg); \
        cp16(sb + OF_L + (buf)*9216 + (crow+32)*144 + cseg,  bL + (size_t)(crow+32)*1024 + cseg); \
    } while (0)
    VCOPY(0, 0); CP_COMMIT();

    // ---- softmax ----
    float val[4][16];
    #pragma unroll
    for (int i = 0; i < 4; i++) {
        int r = w * 4 + i;
        int q = q0 + r;
        size_t arow = ((size_t)bh * S_ + q) * S_;
        size_t mrow = ((size_t)b  * S_ + q) * S_;
        float mx = -3.0e38f;
        #pragma unroll
        for (int j = 0; j < 16; j++) {
            int k = l + 32*j;
            float v = sc[r*520 + k] + g_attn[arow + k];
            if (mask[mrow + k] != 0u) v = -1e18f;
            val[i][j] = v;
            mx = fmaxf(mx, v);
        }
        #pragma unroll
        for (int o = 16; o > 0; o >>= 1) mx = fmaxf(mx, __shfl_xor_sync(0xffffffffu, mx, o));
        float s = 0.f;
        #pragma unroll
        for (int j = 0; j < 16; j++) {
            float e = __expf(val[i][j] - mx);
            val[i][j] = e;
            s += e;
        }
        #pragma unroll
        for (int o = 16; o > 0; o >>= 1) s += __shfl_xor_sync(0xffffffffu, s, o);
        float inv = 1.0f / s;
        #pragma unroll
        for (int j = 0; j < 16; j++) val[i][j] *= inv;
    }
    __syncthreads();   // ALL warps done reading sc before Ph/Pl overlay (cross-warp!)

    #pragma unroll
    for (int i = 0; i < 4; i++) {
        int r = w * 4 + i;
        int q = q0 + r;
        size_t arow = ((size_t)bh * S_ + q) * S_;
        size_t mrow = ((size_t)b  * S_ + q) * S_;
        #pragma unroll
        for (int j = 0; j < 16; j++) {
            int k = l + 32*j;
            float e = val[i][j];
            g_attn[arow + k] = e;
            if (h == 0) top_out[mrow + k] = e;
            __nv_bfloat16 ph, pl;
            split_bf16(e, ph, pl);
            sPh[r*520 + k] = ph;
            sPl[r*520 + k] = pl;
        }
    }

    // ---- P @ V: 8 chunks of 64 k, double-buffered ----
    float C2[2][4];
    #pragma unroll
    for (int mf = 0; mf < 2; mf++)
        #pragma unroll
        for (int p = 0; p < 4; p++) C2[mf][p] = 0.f;

    for (int c = 0; c < 8; c++) {
        const int buf = c & 1;
        if (c < 7) { VCOPY(c + 1, buf ^ 1); CP_COMMIT();
                     asm volatile("cp.async.wait_group 1;"); }
        else       { asm volatile("cp.async.wait_group 0;"); }
        __syncthreads();

        const __nv_bfloat16* vbh = (const __nv_bfloat16*)(smem + OF_H + buf*9216);
        const __nv_bfloat16* vbl = (const __nv_bfloat16*)(smem + OF_L + buf*9216);

        #pragma unroll
        for (int ks = 0; ks < 4; ks++) {
            const int kc = ks * 16 + lr * 2;
            const int kg = c * 64 + kc;
            uint32_t aph[2][4], apl[2][4];
            #pragma unroll
            for (int mf = 0; mf < 2; mf++) {
                int r = mf * 16 + lq;
                aph[mf][0] = *(const uint32_t*)&sPh[r*520 + kg];
                aph[mf][1] = *(const uint32_t*)&sPh[(r+8)*520 + kg];
                aph[mf][2] = *(const uint32_t*)&sPh[r*520 + kg + 8];
                aph[mf][3] = *(const uint32_t*)&sPh[(r+8)*520 + kg + 8];
                apl[mf][0] = *(const uint32_t*)&sPl[r*520 + kg];
                apl[mf][1] = *(const uint32_t*)&sPl[(r+8)*520 + kg];
                apl[mf][2] = *(const uint32_t*)&sPl[r*520 + kg + 8];
                apl[mf][3] = *(const uint32_t*)&sPl[(r+8)*520 + kg + 8];
            }
            uint32_t bvh[2], bvl[2];
            int n = w * 8 + lq;
            bvh[0] = *(const uint32_t*)&vbh[n*72 + kc];
            bvh[1] = *(const uint32_t*)&vbh[n*72 + kc + 8];
            bvl[0] = *(const uint32_t*)&vbl[n*72 + kc];
            bvl[1] = *(const uint32_t*)&vbl[n*72 + kc + 8];
            #pragma unroll
            for (int mf = 0; mf < 2; mf++) {
                mma_bf16(C2[mf], aph[mf], bvh);
                mma_bf16(C2[mf], aph[mf], bvl);
                mma_bf16(C2[mf], apl[mf], bvh);
            }
        }
        __syncthreads();
    }

    #pragma unroll
    for (int mf = 0; mf < 2; mf++) {
        int row = q0 + mf * 16 + lq;
        int col = w * 8 + lr * 2;
        *(float2*)&g_ctxa[((size_t)bh*S_ + row)*DH_ + col]     = make_float2(C2[mf][0], C2[mf][1]);
        *(float2*)&g_ctxa[((size_t)bh*S_ + row + 8)*DH_ + col] = make_float2(C2[mf][2], C2[mf][3]);
    }
}

// ============================================================
// ast partials: g_astp[ks][b,h,q,c] = sum over k in [ks*128,+128)
// ============================================================
__global__ void ast_kernel(const float* __restrict__ structure)
{
    int b = blockIdx.y, q0 = blockIdx.x * 8, ksp = blockIdx.z;
    __shared__ float sA[8][12][33];
    __shared__ float sS[32][8][33];
    int t = threadIdx.x;
    bool active = t < 120;
    int qq = 0, h0 = 0, c0 = 0;
    if (active) { qq = t / 15; int g = t % 15; h0 = (g / 5) * 4; c0 = (g % 5) * 6; }
    float acc[4][6] = {};

    for (int k0 = ksp * 128; k0 < ksp * 128 + 128; k0 += 32) {
        __syncthreads();
        for (int i = t; i < 8*12*32; i += 128) {
            int iq = i / 384; int r = i % 384; int ih = r >> 5; int ik = r & 31;
            sA[iq][ih][ik] = g_attn[(((size_t)b*H_ + ih)*S_ + q0 + iq)*S_ + k0 + ik];
        }
        for (int i = t; i < 8*32*30; i += 128) {
            int iq = i / 960; int r = i % 960; int ik = r / 30; int c = r % 30;
            sS[ik][iq][c] = structure[((size_t)(b*S_ + q0 + iq)*S_ + k0 + ik)*SD_ + c];
        }
        __syncthreads();
        if (active) {
            #pragma unroll 4
            for (int kk = 0; kk < 32; kk++) {
                float av[4], sv[6];
                #pragma unroll
                for (int i = 0; i < 4; i++) av[i] = sA[qq][h0 + i][kk];
                #pragma unroll
                for (int j = 0; j < 6; j++) sv[j] = sS[kk][qq][c0 + j];
                #pragma unroll
                for (int i = 0; i < 4; i++)
                    #pragma unroll
                    for (int j = 0; j < 6; j++)
                        acc[i][j] += av[i] * sv[j];
            }
        }
    }
    if (active) {
        #pragma unroll
        for (int i = 0; i < 4; i++)
            #pragma unroll
            for (int j = 0; j < 6; j++)
                g_astp[ksp][(((size_t)b*H_ + h0 + i)*S_ + q0 + qq)*SD_ + c0 + j] = acc[i][j];
    }
}

// ============================================================
// merge: g_ctx = ctxa + (sum_ks astp)@Wsv + bsv
// ============================================================
__global__ void ctx2_kernel(const float* __restrict__ Wsv, const float* __restrict__ bsv)
{
    int idx = blockIdx.x * 256 + threadIdx.x;
    if (idx >= B_*H_*S_*DH_) return;
    int d = idx & 63, row = idx >> 6;
    float acc = g_ctxa[idx] + bsv[d];
    const float* a0 = g_astp[0] + (size_t)row * SD_;
    const float* a1 = g_astp[1] + (size_t)row * SD_;
    const float* a2 = g_astp[2] + (size_t)row * SD_;
    const float* a3 = g_astp[3] + (size_t)row * SD_;
    #pragma unroll
    for (int c = 0; c < SD_; c++) {
        float s = a0[c] + a1[c] + a2[c] + a3[c];
        acc += s * Wsv[c*DH_ + d];
    }
    int s = row % S_, h = (row / S_) % H_, b = row / (S_ * H_);
    g_ctx[((size_t)b*S_ + s)*D_ + h*DH_ + d] = acc;
}

// ============================================================
extern "C" void kernel_launch(void* const* d_in, const int* in_sizes, int n_in,
                              void* d_out, int out_size)
{
    const float* key       = (const float*)d_in[0];
    const float* value     = (const float*)d_in[1];
    const float* query     = (const float*)d_in[2];
    const float* structure = (const float*)d_in[3];
    const unsigned int* mask = (const unsigned int*)d_in[4];
    const float* Wq  = (const float*)d_in[5];
    const float* bq  = (const float*)d_in[6];
    const float* Wk  = (const float*)d_in[7];
    const float* bk  = (const float*)d_in[8];
    const float* Wv  = (const float*)d_in[9];
    const float* bv  = (const float*)d_in[10];
    const float* Wsk = (const float*)d_in[11];
    const float* bsk = (const float*)d_in[12];
    const float* Wsv = (const float*)d_in[13];
    const float* bsv = (const float*)d_in[14];
    const float* Wo  = (const float*)d_in[15];
    const float* bo  = (const float*)d_in[16];
    float* out = (float*)d_out;

    cudaFuncSetAttribute(attn2_kernel, cudaFuncAttributeMaxDynamicSharedMemorySize, AT_SMEM);

    gemm_mma<0><<<dim3(12, 16, 3), 256>>>(query, key, value, Wq, Wk, Wv, bq, bk, bv, nullptr); // 1: fused QKV
    qws2_kernel<<<768, 128>>>(Wsk, bsk);                       // 2
    struct_score_kernel<<<dim3(4, 512, 4), 128>>>(structure);  // 3
    attn2_kernel<<<dim3(16, 48), 256, AT_SMEM>>>(mask, out + (size_t)B_*S_*D_); // 4 (profiled, control)
    ast_kernel<<<dim3(64, 4, 4), 128>>>(structure);            // 5
    ctx2_kernel<<<6144, 256>>>(Wsv, bsv);                      // 6
    gemm_mma<1><<<dim3(12, 16, 2), 256>>>(nullptr, nullptr, nullptr, Wo, nullptr, nullptr,
                                          bo, nullptr, nullptr, nullptr);  // 7: out proj split-K
    opmerge_kernel<<<1536, 256>>>(out);                        // 8: merge partials
}

// round 16
// speedup vs baseline: 1.4202x; 1.4202x over previous
#include <cuda_runtime.h>
#include <cuda_bf16.h>
#include <stdint.h>
#include <math.h>

#define B_  4
#define S_  512
#define D_  768
#define H_  12
#define DH_ 64
#define SD_ 30
#define BS_ (B_*S_)   // 2048

// ---- scratch ----
__device__ float g_q  [B_*H_*S_*DH_];                 // fp32 q (for qws)
__device__ __nv_bfloat16 g_qh [B_*H_*S_*DH_];         // bf16 splits, (bh,s,d)
__device__ __nv_bfloat16 g_ql [B_*H_*S_*DH_];
__device__ __nv_bfloat16 g_kh [B_*H_*S_*DH_];
__device__ __nv_bfloat16 g_kl [B_*H_*S_*DH_];
__device__ __nv_bfloat16 g_vhT[B_*H_*S_*DH_];         // transposed (bh,d,s)
__device__ __nv_bfloat16 g_vlT[B_*H_*S_*DH_];
__device__ float g_qws[B_*H_*S_*SD_];
__device__ float g_qb [B_*H_*S_];
__device__ float g_attn[(size_t)B_*H_*S_*S_];
__device__ float g_ctxa[B_*H_*S_*DH_];
__device__ float g_astp[4][B_*H_*S_*SD_];             // k-split partials
__device__ float g_ctx [BS_*D_];

// ================= helpers =================
__device__ __forceinline__ void mma_bf16(float* c, const uint32_t* a, const uint32_t* b) {
    asm volatile("mma.sync.aligned.m16n8k16.row.col.f32.bf16.bf16.f32 "
        "{%0,%1,%2,%3}, {%4,%5,%6,%7}, {%8,%9}, {%0,%1,%2,%3};"
        : "+f"(c[0]), "+f"(c[1]), "+f"(c[2]), "+f"(c[3])
        : "r"(a[0]), "r"(a[1]), "r"(a[2]), "r"(a[3]), "r"(b[0]), "r"(b[1]));
}
__device__ __forceinline__ void split_bf16(float x, __nv_bfloat16& h, __nv_bfloat16& l) {
    h = __float2bfloat16(x);
    l = __float2bfloat16(x - __bfloat162float(h));
}
__device__ __forceinline__ uint32_t pack_bf2(__nv_bfloat16 a, __nv_bfloat16 b) {
    return (uint32_t)__bfloat16_as_ushort(a) | ((uint32_t)__bfloat16_as_ushort(b) << 16);
}
__device__ __forceinline__ uint32_t smem_u32(const void* p) {
    uint32_t a;
    asm("{ .reg .u64 t; cvta.to.shared.u64 t, %1; cvt.u32.u64 %0, t; }" : "=r"(a) : "l"(p));
    return a;
}
__device__ __forceinline__ void cp16(uint32_t dst, const void* src) {
    asm volatile("cp.async.cg.shared.global [%0], [%1], 16;" :: "r"(dst), "l"(src));
}
#define CP_COMMIT() asm volatile("cp.async.commit_group;")

// ============================================================
// HMMA bf16-split GEMM (R10 structure).
// MODE 0: blockIdx.z selects q/k/v projection (fused launch).
// MODE 1: X=g_ctx -> extout.
// ============================================================
template<int MODE>
__global__ void __launch_bounds__(256) gemm_mma(
    const float* __restrict__ Aq, const float* __restrict__ Ak, const float* __restrict__ Av,
    const float* __restrict__ Wq_, const float* __restrict__ Wk_, const float* __restrict__ Wv_,
    const float* __restrict__ bq_, const float* __restrict__ bk_, const float* __restrict__ bv_,
    float* __restrict__ extout)
{
    __shared__ __nv_bfloat16 sAh[128][40];
    __shared__ __nv_bfloat16 sAl[128][40];
    __shared__ __nv_bfloat16 sBh[64][40];
    __shared__ __nv_bfloat16 sBl[64][40];

    const int t = threadIdx.x;
    const int z = (MODE == 0) ? blockIdx.z : 0;

    const float* X; const float* W; const float* bias; float scale = 1.0f;
    if (MODE == 0) {
        X    = (z == 0) ? Aq  : (z == 1) ? Ak  : Av;
        W    = (z == 0) ? Wq_ : (z == 1) ? Wk_ : Wv_;
        bias = (z == 0) ? bq_ : (z == 1) ? bk_ : bv_;
        if (z == 0) scale = 0.125f;
    } else {
        X = g_ctx; W = Wq_; bias = bq_;
    }
    const int m0 = blockIdx.y * 128, n0 = blockIdx.x * 64;
    const int w = t >> 5, l = t & 31;
    const int wm = (w >> 1) * 32, wn = (w & 1) * 32;
    const int lq = l >> 2, lr = l & 3;

    float C[2][4][4];
    #pragma unroll
    for (int i = 0; i < 2; i++)
        #pragma unroll
        for (int j = 0; j < 4; j++)
            #pragma unroll
            for (int p = 0; p < 4; p++) C[i][j][p] = 0.f;

    for (int k0 = 0; k0 < 768; k0 += 32) {
        __syncthreads();
        #pragma unroll
        for (int it = 0; it < 4; it++) {
            int f = t + it * 256;
            int m = f >> 3, k4 = (f & 7) * 4;
            float4 v = *(const float4*)(X + (size_t)(m0 + m) * 768 + k0 + k4);
            __nv_bfloat16 h0,h1,h2,h3, l0,l1,l2,l3;
            split_bf16(v.x, h0, l0); split_bf16(v.y, h1, l1);
            split_bf16(v.z, h2, l2); split_bf16(v.w, h3, l3);
            *(uint2*)&sAh[m][k4] = make_uint2(pack_bf2(h0,h1), pack_bf2(h2,h3));
            *(uint2*)&sAl[m][k4] = make_uint2(pack_bf2(l0,l1), pack_bf2(l2,l3));
        }
        #pragma unroll
        for (int it = 0; it < 2; it++) {
            int f = t + it * 256;
            int kk = f >> 4, n4 = (f & 15) * 4;
            float4 v = *(const float4*)(W + (size_t)(k0 + kk) * 768 + n0 + n4);
            __nv_bfloat16 h, lo;
            split_bf16(v.x, h, lo); sBh[n4+0][kk] = h; sBl[n4+0][kk] = lo;
            split_bf16(v.y, h, lo); sBh[n4+1][kk] = h; sBl[n4+1][kk] = lo;
            split_bf16(v.z, h, lo); sBh[n4+2][kk] = h; sBl[n4+2][kk] = lo;
            split_bf16(v.w, h, lo); sBh[n4+3][kk] = h; sBl[n4+3][kk] = lo;
        }
        __syncthreads();

        #pragma unroll
        for (int s = 0; s < 2; s++) {
            const int kc = s * 16 + lr * 2;
            uint32_t ah[2][4], al[2][4];
            #pragma unroll
            for (int i = 0; i < 2; i++) {
                int r = wm + i * 16 + lq;
                ah[i][0] = *(const uint32_t*)&sAh[r][kc];
                ah[i][1] = *(const uint32_t*)&sAh[r + 8][kc];
                ah[i][2] = *(const uint32_t*)&sAh[r][kc + 8];
                ah[i][3] = *(const uint32_t*)&sAh[r + 8][kc + 8];
                al[i][0] = *(const uint32_t*)&sAl[r][kc];
                al[i][1] = *(const uint32_t*)&sAl[r + 8][kc];
                al[i][2] = *(const uint32_t*)&sAl[r][kc + 8];
                al[i][3] = *(const uint32_t*)&sAl[r + 8][kc + 8];
            }
            uint32_t bh[4][2], bl[4][2];
            #pragma unroll
            for (int j = 0; j < 4; j++) {
                int n = wn + j * 8 + lq;
                bh[j][0] = *(const uint32_t*)&sBh[n][kc];
                bh[j][1] = *(const uint32_t*)&sBh[n][kc + 8];
                bl[j][0] = *(const uint32_t*)&sBl[n][kc];
                bl[j][1] = *(const uint32_t*)&sBl[n][kc + 8];
            }
            #pragma unroll
            for (int i = 0; i < 2; i++)
                #pragma unroll
                for (int j = 0; j < 4; j++) {
                    mma_bf16(C[i][j], ah[i], bh[j]);
                    mma_bf16(C[i][j], ah[i], bl[j]);
                    mma_bf16(C[i][j], al[i], bh[j]);
                }
        }
    }

    #pragma unroll
    for (int i = 0; i < 2; i++) {
        #pragma unroll
        for (int j = 0; j < 4; j++) {
            int rA = m0 + wm + i * 16 + lq;
            int cA = n0 + wn + j * 8 + lr * 2;
            #pragma unroll
            for (int half = 0; half < 2; half++) {
                int m = rA + half * 8;
                float v0 = (C[i][j][half*2 + 0] + bias[cA])     * scale;
                float v1 = (C[i][j][half*2 + 1] + bias[cA + 1]) * scale;
                if (MODE == 0) {
                    int b_i = m >> 9, s = m & 511, h = cA >> 6, d = cA & 63;
                    size_t base = (((size_t)b_i * H_ + h) * S_ + s) * DH_ + d;
                    __nv_bfloat16 h0, l0, h1, l1;
                    split_bf16(v0, h0, l0); split_bf16(v1, h1, l1);
                    if (z == 0) {
                        *(float2*)(g_q + base) = make_float2(v0, v1);
                        *(uint32_t*)&g_qh[base] = pack_bf2(h0, h1);
                        *(uint32_t*)&g_ql[base] = pack_bf2(l0, l1);
                    } else if (z == 1) {
                        *(uint32_t*)&g_kh[base] = pack_bf2(h0, h1);
                        *(uint32_t*)&g_kl[base] = pack_bf2(l0, l1);
                    } else {
                        size_t tb = ((size_t)(b_i * H_ + h) * DH_ + d) * S_ + s;
                        g_vhT[tb] = h0; g_vhT[tb + S_] = h1;
                        g_vlT[tb] = l0; g_vlT[tb + S_] = l1;
                    }
                } else {
                    *(float2*)(extout + (size_t)m * 768 + cA) = make_float2(v0, v1);
                }
            }
        }
    }
}

// ============================================================
// qws: smem-tiled
// ============================================================
__global__ void __launch_bounds__(128) qws2_kernel(const float* __restrict__ Wsk,
                                                   const float* __restrict__ bsk)
{
    __shared__ float sq[32][65];
    __shared__ float sw[31][64];
    const int t = threadIdx.x;
    const int r0 = blockIdx.x * 32;

    #pragma unroll
    for (int i = 0; i < 4; i++) {
        int f = t + i * 128;
        int r = f >> 4, c4 = (f & 15) * 4;
        float4 v = *(const float4*)(g_q + (size_t)(r0 + r) * 64 + c4);
        sq[r][c4] = v.x; sq[r][c4+1] = v.y; sq[r][c4+2] = v.z; sq[r][c4+3] = v.w;
    }
    #pragma unroll
    for (int i = 0; i < 4; i++) {
        int f = t + i * 128;
        if (f < 496) {
            int c = f >> 4, d4 = (f & 15) * 4;
            float4 v = (c < 30) ? *(const float4*)(Wsk + c * 64 + d4)
                                : *(const float4*)(bsk + d4);
            sw[c][d4] = v.x; sw[c][d4+1] = v.y; sw[c][d4+2] = v.z; sw[c][d4+3] = v.w;
        }
    }
    __syncthreads();

    const int row = t & 31;
    const int grp = t >> 5;
    const int c0 = grp * 8;
    float acc[8] = {};
    #pragma unroll
    for (int d = 0; d < 64; d++) {
        float qv = sq[row][d];
        #pragma unroll
        for (int j = 0; j < 8; j++) {
            int c = c0 + j;
            if (j < 7 || grp < 3) {
                float wv = (c < 30) ? sw[c][d] : sw[30][d];
                acc[j] += qv * wv;
            }
        }
    }
    int rg = r0 + row;
    if (grp < 3) {
        #pragma unroll
        for (int j = 0; j < 8; j++) g_qws[(size_t)rg*SD_ + c0 + j] = acc[j];
    } else {
        #pragma unroll
        for (int j = 0; j < 6; j++) g_qws[(size_t)rg*SD_ + 24 + j] = acc[j];
        g_qb[rg] = acc[6];
    }
}

// ============================================================
// struct scores prepass
// ============================================================
__global__ void struct_score_kernel(const float* __restrict__ structure)
{
    int b = blockIdx.z, q = blockIdx.y;
    int k = blockIdx.x * 128 + threadIdx.x;
    __shared__ float qw[H_][SD_];
    __shared__ float qb[H_];
    int t = threadIdx.x;
    for (int i = t; i < H_*SD_; i += 128) {
        int h = i / SD_, c = i % SD_;
        qw[h][c] = g_qws[(((size_t)b*H_ + h)*S_ + q)*SD_ + c];
    }
    if (t < H_) qb[t] = g_qb[((size_t)b*H_ + t)*S_ + q];
    __syncthreads();

    const float* st = structure + ((size_t)(b*S_ + q)*S_ + k) * SD_;
    float sv[SD_];
    #pragma unroll
    for (int c = 0; c < SD_; c += 2) {
        float2 v = *(const float2*)(st + c);
        sv[c] = v.x; sv[c+1] = v.y;
    }
    #pragma unroll
    for (int h = 0; h < H_; h++) {
        float acc = qb[h];
        #pragma unroll
        for (int c = 0; c < SD_; c++) acc += sv[c] * qw[h][c];
        g_attn[(((size_t)b*H_ + h)*S_ + q)*S_ + k] = acc;
    }
}

// ============================================================
// attn2 rev3b: cp.async double-buffered K/V; QK^T + bias + mask +
// softmax + P@V. Block = (b,h) x 32 q-rows, 256 threads.
// ============================================================
#define AT_SMEM 112640
__global__ void __launch_bounds__(256) attn2_kernel(const unsigned int* __restrict__ mask,
                                                    float* __restrict__ top_out)
{
    extern __shared__ char smem[];
    uint32_t sb = smem_u32(smem);
    float*          sc  = (float*)smem;
    __nv_bfloat16*  sPh = (__nv_bfloat16*)smem;
    __nv_bfloat16*  sPl = (__nv_bfloat16*)(smem + 33280);
    __nv_bfloat16*  sQh = (__nv_bfloat16*)(smem + 66560);
    __nv_bfloat16*  sQl = (__nv_bfloat16*)(smem + 71168);
    const uint32_t OF_H = 75776, OF_L = 94208;   // + buf*9216

    const int bh = blockIdx.y;
    const int b  = bh / H_;
    const int h  = bh % H_;
    const int q0 = blockIdx.x * 32;
    const __nv_bfloat16* Qh = g_qh  + (size_t)bh * S_ * DH_;
    const __nv_bfloat16* Ql = g_ql  + (size_t)bh * S_ * DH_;
    const __nv_bfloat16* Kh = g_kh  + (size_t)bh * S_ * DH_;
    const __nv_bfloat16* Kl = g_kl  + (size_t)bh * S_ * DH_;
    const __nv_bfloat16* VhT = g_vhT + (size_t)bh * S_ * DH_;   // (d,s)
    const __nv_bfloat16* VlT = g_vlT + (size_t)bh * S_ * DH_;

    const int t = threadIdx.x;
    const int w = t >> 5, l = t & 31;
    const int lq = l >> 2, lr = l & 3;
    const int crow = t >> 3, cseg = (t & 7) * 16;     // copy mapping

    // ---- stage Q ----
    {
        int row = t >> 3, d8 = (t & 7) * 8;
        *(uint4*)&sQh[row*72 + d8] = *(const uint4*)(Qh + (size_t)(q0 + row)*64 + d8);
        *(uint4*)&sQl[row*72 + d8] = *(const uint4*)(Ql + (size_t)(q0 + row)*64 + d8);
    }

    // ---- QK^T: 8 chunks of 64 k-rows, double-buffered cp.async ----
    #define KCOPY(c, buf) do { \
        const char* bH = (const char*)Kh + (size_t)(c)*8192; \
        const char* bL = (const char*)Kl + (size_t)(c)*8192; \
        cp16(sb + OF_H + (buf)*9216 + crow*144 + cseg,       bH + crow*128 + cseg); \
        cp16(sb + OF_H + (buf)*9216 + (crow+32)*144 + cseg,  bH + (crow+32)*128 + cseg); \
        cp16(sb + OF_L + (buf)*9216 + crow*144 + cseg,       bL + crow*128 + cseg); \
        cp16(sb + OF_L + (buf)*9216 + (crow+32)*144 + cseg,  bL + (crow+32)*128 + cseg); \
    } while (0)

    KCOPY(0, 0); CP_COMMIT();
    for (int c = 0; c < 8; c++) {
        const int buf = c & 1;
        if (c < 7) { KCOPY(c + 1, buf ^ 1); CP_COMMIT();
                     asm volatile("cp.async.wait_group 1;"); }
        else       { asm volatile("cp.async.wait_group 0;"); }
        __syncthreads();

        const __nv_bfloat16* kbh = (const __nv_bfloat16*)(smem + OF_H + buf*9216);
        const __nv_bfloat16* kbl = (const __nv_bfloat16*)(smem + OF_L + buf*9216);

        float C[2][4];
        #pragma unroll
        for (int i = 0; i < 2; i++)
            #pragma unroll
            for (int p = 0; p < 4; p++) C[i][p] = 0.f;

        #pragma unroll
        for (int ks = 0; ks < 4; ks++) {
            const int kc = ks * 16 + lr * 2;
            uint32_t ah[2][4], al[2][4];
            #pragma unroll
            for (int mf = 0; mf < 2; mf++) {
                int r = mf * 16 + lq;
                ah[mf][0] = *(const uint32_t*)&sQh[r*72 + kc];
                ah[mf][1] = *(const uint32_t*)&sQh[(r+8)*72 + kc];
                ah[mf][2] = *(const uint32_t*)&sQh[r*72 + kc + 8];
                ah[mf][3] = *(const uint32_t*)&sQh[(r+8)*72 + kc + 8];
                al[mf][0] = *(const uint32_t*)&sQl[r*72 + kc];
                al[mf][1] = *(const uint32_t*)&sQl[(r+8)*72 + kc];
                al[mf][2] = *(const uint32_t*)&sQl[r*72 + kc + 8];
                al[mf][3] = *(const uint32_t*)&sQl[(r+8)*72 + kc + 8];
            }
            uint32_t bhf[2], blf[2];
            int n = w * 8 + lq;
            bhf[0] = *(const uint32_t*)&kbh[n*72 + kc];
            bhf[1] = *(const uint32_t*)&kbh[n*72 + kc + 8];
            blf[0] = *(const uint32_t*)&kbl[n*72 + kc];
            blf[1] = *(const uint32_t*)&kbl[n*72 + kc + 8];
            #pragma unroll
            for (int mf = 0; mf < 2; mf++) {
                mma_bf16(C[mf], ah[mf], bhf);
                mma_bf16(C[mf], ah[mf], blf);
                mma_bf16(C[mf], al[mf], bhf);
            }
        }
        #pragma unroll
        for (int mf = 0; mf < 2; mf++) {
            int col = c * 64 + w * 8 + lr * 2;
            int r = mf * 16 + lq;
            *(float2*)&sc[r*520 + col]     = make_float2(C[mf][0], C[mf][1]);
            *(float2*)&sc[(r+8)*520 + col] = make_float2(C[mf][2], C[mf][3]);
        }
        __syncthreads();
    }

    // ---- prefetch V chunk 0 (overlaps softmax) ----
    #define VCOPY(c, buf) do { \
        const char* bH = (const char*)VhT + (size_t)(c)*128; \
        const char* bL = (const char*)VlT + (size_t)(c)*128; \
        cp16(sb + OF_H + (buf)*9216 + crow*144 + cseg,       bH + (size_t)crow*1024 + cseg); \
        cp16(sb + OF_H + (buf)*9216 + (crow+32)*144 + cseg,  bH + (size_t)(crow+32)*1024 + cseg); \
        cp16(sb + OF_L + (buf)*9216 + crow*144 + cseg,       bL + (size_t)crow*1024 + cseg); \
        cp16(sb + OF_L + (buf)*9216 + (crow+32)*144 + cseg,  bL + (size_t)(crow+32)*1024 + cseg); \
    } while (0)
    VCOPY(0, 0); CP_COMMIT();

    // ---- softmax ----
    float val[4][16];
    #pragma unroll
    for (int i = 0; i < 4; i++) {
        int r = w * 4 + i;
        int q = q0 + r;
        size_t arow = ((size_t)bh * S_ + q) * S_;
        size_t mrow = ((size_t)b  * S_ + q) * S_;
        float mx = -3.0e38f;
        #pragma unroll
        for (int j = 0; j < 16; j++) {
            int k = l + 32*j;
            float v = sc[r*520 + k] + g_attn[arow + k];
            if (mask[mrow + k] != 0u) v = -1e18f;
            val[i][j] = v;
            mx = fmaxf(mx, v);
        }
        #pragma unroll
        for (int o = 16; o > 0; o >>= 1) mx = fmaxf(mx, __shfl_xor_sync(0xffffffffu, mx, o));
        float s = 0.f;
        #pragma unroll
        for (int j = 0; j < 16; j++) {
            float e = __expf(val[i][j] - mx);
            val[i][j] = e;
            s += e;
        }
        #pragma unroll
        for (int o = 16; o > 0; o >>= 1) s += __shfl_xor_sync(0xffffffffu, s, o);
        float inv = 1.0f / s;
        #pragma unroll
        for (int j = 0; j < 16; j++) val[i][j] *= inv;
    }
    __syncthreads();   // ALL warps done reading sc before Ph/Pl overlay (cross-warp!)

    #pragma unroll
    for (int i = 0; i < 4; i++) {
        int r = w * 4 + i;
        int q = q0 + r;
        size_t arow = ((size_t)bh * S_ + q) * S_;
        size_t mrow = ((size_t)b  * S_ + q) * S_;
        #pragma unroll
        for (int j = 0; j < 16; j++) {
            int k = l + 32*j;
            float e = val[i][j];
            g_attn[arow + k] = e;
            if (h == 0) top_out[mrow + k] = e;
            __nv_bfloat16 ph, pl;
            split_bf16(e, ph, pl);
            sPh[r*520 + k] = ph;
            sPl[r*520 + k] = pl;
        }
    }

    // ---- P @ V: 8 chunks of 64 k, double-buffered ----
    float C2[2][4];
    #pragma unroll
    for (int mf = 0; mf < 2; mf++)
        #pragma unroll
        for (int p = 0; p < 4; p++) C2[mf][p] = 0.f;

    for (int c = 0; c < 8; c++) {
        const int buf = c & 1;
        if (c < 7) { VCOPY(c + 1, buf ^ 1); CP_COMMIT();
                     asm volatile("cp.async.wait_group 1;"); }
        else       { asm volatile("cp.async.wait_group 0;"); }
        __syncthreads();

        const __nv_bfloat16* vbh = (const __nv_bfloat16*)(smem + OF_H + buf*9216);
        const __nv_bfloat16* vbl = (const __nv_bfloat16*)(smem + OF_L + buf*9216);

        #pragma unroll
        for (int ks = 0; ks < 4; ks++) {
            const int kc = ks * 16 + lr * 2;
            const int kg = c * 64 + kc;
            uint32_t aph[2][4], apl[2][4];
            #pragma unroll
            for (int mf = 0; mf < 2; mf++) {
                int r = mf * 16 + lq;
                aph[mf][0] = *(const uint32_t*)&sPh[r*520 + kg];
                aph[mf][1] = *(const uint32_t*)&sPh[(r+8)*520 + kg];
                aph[mf][2] = *(const uint32_t*)&sPh[r*520 + kg + 8];
                aph[mf][3] = *(const uint32_t*)&sPh[(r+8)*520 + kg + 8];
                apl[mf][0] = *(const uint32_t*)&sPl[r*520 + kg];
                apl[mf][1] = *(const uint32_t*)&sPl[(r+8)*520 + kg];
                apl[mf][2] = *(const uint32_t*)&sPl[r*520 + kg + 8];
                apl[mf][3] = *(const uint32_t*)&sPl[(r+8)*520 + kg + 8];
            }
            uint32_t bvh[2], bvl[2];
            int n = w * 8 + lq;
            bvh[0] = *(const uint32_t*)&vbh[n*72 + kc];
            bvh[1] = *(const uint32_t*)&vbh[n*72 + kc + 8];
            bvl[0] = *(const uint32_t*)&vbl[n*72 + kc];
            bvl[1] = *(const uint32_t*)&vbl[n*72 + kc + 8];
            #pragma unroll
            for (int mf = 0; mf < 2; mf++) {
                mma_bf16(C2[mf], aph[mf], bvh);
                mma_bf16(C2[mf], aph[mf], bvl);
                mma_bf16(C2[mf], apl[mf], bvh);
            }
        }
        __syncthreads();
    }

    #pragma unroll
    for (int mf = 0; mf < 2; mf++) {
        int row = q0 + mf * 16 + lq;
        int col = w * 8 + lr * 2;
        *(float2*)&g_ctxa[((size_t)bh*S_ + row)*DH_ + col]     = make_float2(C2[mf][0], C2[mf][1]);
        *(float2*)&g_ctxa[((size_t)bh*S_ + row + 8)*DH_ + col] = make_float2(C2[mf][2], C2[mf][3]);
    }
}

// ============================================================
// ast partials: g_astp[ks][b,h,q,c] = sum over k in [ks*128,+128)
// ============================================================
__global__ void ast_kernel(const float* __restrict__ structure)
{
    int b = blockIdx.y, q0 = blockIdx.x * 8, ksp = blockIdx.z;
    __shared__ float sA[8][12][33];
    __shared__ float sS[32][8][33];
    int t = threadIdx.x;
    bool active = t < 120;
    int qq = 0, h0 = 0, c0 = 0;
    if (active) { qq = t / 15; int g = t % 15; h0 = (g / 5) * 4; c0 = (g % 5) * 6; }
    float acc[4][6] = {};

    for (int k0 = ksp * 128; k0 < ksp * 128 + 128; k0 += 32) {
        __syncthreads();
        for (int i = t; i < 8*12*32; i += 128) {
            int iq = i / 384; int r = i % 384; int ih = r >> 5; int ik = r & 31;
            sA[iq][ih][ik] = g_attn[(((size_t)b*H_ + ih)*S_ + q0 + iq)*S_ + k0 + ik];
        }
        for (int i = t; i < 8*32*30; i += 128) {
            int iq = i / 960; int r = i % 960; int ik = r / 30; int c = r % 30;
            sS[ik][iq][c] = structure[((size_t)(b*S_ + q0 + iq)*S_ + k0 + ik)*SD_ + c];
        }
        __syncthreads();
        if (active) {
            #pragma unroll 4
            for (int kk = 0; kk < 32; kk++) {
                float av[4], sv[6];
                #pragma unroll
                for (int i = 0; i < 4; i++) av[i] = sA[qq][h0 + i][kk];
                #pragma unroll
                for (int j = 0; j < 6; j++) sv[j] = sS[kk][qq][c0 + j];
                #pragma unroll
                for (int i = 0; i < 4; i++)
                    #pragma unroll
                    for (int j = 0; j < 6; j++)
                        acc[i][j] += av[i] * sv[j];
            }
        }
    }
    if (active) {
        #pragma unroll
        for (int i = 0; i < 4; i++)
            #pragma unroll
            for (int j = 0; j < 6; j++)
                g_astp[ksp][(((size_t)b*H_ + h0 + i)*S_ + q0 + qq)*SD_ + c0 + j] = acc[i][j];
    }
}

// ============================================================
// merge: g_ctx = ctxa + (sum_ks astp)@Wsv + bsv
// ============================================================
__global__ void ctx2_kernel(const float* __restrict__ Wsv, const float* __restrict__ bsv)
{
    int idx = blockIdx.x * 256 + threadIdx.x;
    if (idx >= B_*H_*S_*DH_) return;
    int d = idx & 63, row = idx >> 6;
    float acc = g_ctxa[idx] + bsv[d];
    const float* a0 = g_astp[0] + (size_t)row * SD_;
    const float* a1 = g_astp[1] + (size_t)row * SD_;
    const float* a2 = g_astp[2] + (size_t)row * SD_;
    const float* a3 = g_astp[3] + (size_t)row * SD_;
    #pragma unroll
    for (int c = 0; c < SD_; c++) {
        float s = a0[c] + a1[c] + a2[c] + a3[c];
        acc += s * Wsv[c*DH_ + d];
    }
    int s = row % S_, h = (row / S_) % H_, b = row / (S_ * H_);
    g_ctx[((size_t)b*S_ + s)*D_ + h*DH_ + d] = acc;
}

// ============================================================
extern "C" void kernel_launch(void* const* d_in, const int* in_sizes, int n_in,
                              void* d_out, int out_size)
{
    const float* key       = (const float*)d_in[0];
    const float* value     = (const float*)d_in[1];
    const float* query     = (const float*)d_in[2];
    const float* structure = (const float*)d_in[3];
    const unsigned int* mask = (const unsigned int*)d_in[4];
    const float* Wq  = (const float*)d_in[5];
    const float* bq  = (const float*)d_in[6];
    const float* Wk  = (const float*)d_in[7];
    const float* bk  = (const float*)d_in[8];
    const float* Wv  = (const float*)d_in[9];
    const float* bv  = (const float*)d_in[10];
    const float* Wsk = (const float*)d_in[11];
    const float* bsk = (const float*)d_in[12];
    const float* Wsv = (const float*)d_in[13];
    const float* bsv = (const float*)d_in[14];
    const float* Wo  = (const float*)d_in[15];
    const float* bo  = (const float*)d_in[16];
    float* out = (float*)d_out;

    cudaFuncSetAttribute(attn2_kernel, cudaFuncAttributeMaxDynamicSharedMemorySize, AT_SMEM);

    gemm_mma<0><<<dim3(12, 16, 3), 256>>>(query, key, value, Wq, Wk, Wv, bq, bk, bv, nullptr); // 1: fused QKV
    qws2_kernel<<<768, 128>>>(Wsk, bsk);                       // 2
    struct_score_kernel<<<dim3(4, 512, 4), 128>>>(structure);  // 3
    attn2_kernel<<<dim3(16, 48), 256, AT_SMEM>>>(mask, out + (size_t)B_*S_*D_); // 4 (profiled, clock canary)
    ast_kernel<<<dim3(64, 4, 4), 128>>>(structure);            // 5
    ctx2_kernel<<<6144, 256>>>(Wsv, bsv);                      // 6
    gemm_mma<1><<<dim3(12, 16, 1), 256>>>(nullptr, nullptr, nullptr, Wo, nullptr, nullptr,
                                          bo, nullptr, nullptr, out);  // 7: out proj
}